// round 1
// baseline (speedup 1.0000x reference)
#include <cuda_runtime.h>
#include <math.h>

#define N_NODES 100000
#define N_EDGES 1600000
#define HF 64
#define HC 32
#define OF 16

// ---------------- scratch (device globals; no runtime allocation) ----------------
__device__ float g_x [(size_t)N_NODES * HF];   // filter-branch linear output
__device__ float g_h1[(size_t)N_NODES * HF];   // tanh MLP branch
__device__ float g_h2[(size_t)N_NODES * HF];   // graph-aggregated branch
__device__ float g_deg_out[N_NODES];
__device__ float g_deg_in [N_NODES];
__device__ float g_inv_out[N_NODES];
__device__ float g_inv_in [N_NODES];
__device__ float g_wsum[2];                    // sum over nodes of attention logits

// ---------------- zero scratch ----------------
__global__ void k_zero() {
    int i = blockIdx.x * blockDim.x + threadIdx.x;
    float4 z = make_float4(0.f, 0.f, 0.f, 0.f);
    if (i < N_NODES * (HF / 4)) reinterpret_cast<float4*>(g_h2)[i] = z;
    if (i < N_NODES) { g_deg_out[i] = 0.f; g_deg_in[i] = 0.f; }
    if (i < 2) g_wsum[i] = 0.f;
}

// ---------------- degree histogram ----------------
__global__ void k_degree(const int* __restrict__ src, const int* __restrict__ dst) {
    int e = blockIdx.x * blockDim.x + threadIdx.x;
    if (e >= N_EDGES) return;
    atomicAdd(&g_deg_out[src[e]], 1.f);
    atomicAdd(&g_deg_in [dst[e]], 1.f);
}

// ---------------- inverse sqrt of degrees ----------------
__global__ void k_invsqrt() {
    int i = blockIdx.x * blockDim.x + threadIdx.x;
    if (i >= N_NODES) return;
    g_inv_out[i] = rsqrtf(fmaxf(g_deg_out[i], 1.f));
    g_inv_in [i] = rsqrtf(fmaxf(g_deg_in [i], 1.f));
}

// ---------------- fused dual GEMM: h1 = tanh(feat@fc1_w^T + b), x = feat@filt_w^T + b ----------------
__global__ __launch_bounds__(128) void k_gemm(
    const float* __restrict__ feat,
    const float* __restrict__ fc1_w, const float* __restrict__ fc1_b,
    const float* __restrict__ filt_w, const float* __restrict__ filt_b)
{
    __shared__ float4 w1s[HF * (HF / 4)];   // fc1_w rows, 16KB
    __shared__ float4 w2s[HF * (HF / 4)];   // filt_w rows, 16KB
    __shared__ float b1s[HF], b2s[HF];

    int tid = threadIdx.x;
    for (int i = tid; i < HF * (HF / 4); i += blockDim.x) {
        w1s[i] = reinterpret_cast<const float4*>(fc1_w)[i];
        w2s[i] = reinterpret_cast<const float4*>(filt_w)[i];
    }
    if (tid < HF) { b1s[tid] = fc1_b[tid]; b2s[tid] = filt_b[tid]; }
    __syncthreads();

    int n = blockIdx.x * blockDim.x + tid;
    if (n >= N_NODES) return;

    float4 f[16];
    const float4* fr = reinterpret_cast<const float4*>(feat + (size_t)n * HF);
#pragma unroll
    for (int i = 0; i < 16; i++) f[i] = fr[i];

    float* out1 = g_h1 + (size_t)n * HF;
    float* out2 = g_x  + (size_t)n * HF;

    for (int j0 = 0; j0 < HF; j0 += 8) {
        float a1[8], a2[8];
#pragma unroll
        for (int u = 0; u < 8; u++) { a1[u] = b1s[j0 + u]; a2[u] = b2s[j0 + u]; }
#pragma unroll
        for (int u = 0; u < 8; u++) {
            const float4* r1 = &w1s[(j0 + u) * 16];
            const float4* r2 = &w2s[(j0 + u) * 16];
#pragma unroll
            for (int i = 0; i < 16; i++) {
                float4 wa = r1[i], wb = r2[i];
                a1[u] += f[i].x * wa.x + f[i].y * wa.y + f[i].z * wa.z + f[i].w * wa.w;
                a2[u] += f[i].x * wb.x + f[i].y * wb.y + f[i].z * wb.z + f[i].w * wb.w;
            }
        }
        float4 o1a = make_float4(tanhf(a1[0]), tanhf(a1[1]), tanhf(a1[2]), tanhf(a1[3]));
        float4 o1b = make_float4(tanhf(a1[4]), tanhf(a1[5]), tanhf(a1[6]), tanhf(a1[7]));
        float4 o2a = make_float4(a2[0], a2[1], a2[2], a2[3]);
        float4 o2b = make_float4(a2[4], a2[5], a2[6], a2[7]);
        *reinterpret_cast<float4*>(out1 + j0)     = o1a;
        *reinterpret_cast<float4*>(out1 + j0 + 4) = o1b;
        *reinterpret_cast<float4*>(out2 + j0)     = o2a;
        *reinterpret_cast<float4*>(out2 + j0 + 4) = o2b;
    }
}

// ---------------- edge gather-scale-scatter: h2[dst] += x[src] * coef ----------------
__device__ __forceinline__ void red_add_v4(float4* addr, float4 v) {
    asm volatile("red.global.add.v4.f32 [%0], {%1,%2,%3,%4};"
                 :: "l"(addr), "f"(v.x), "f"(v.y), "f"(v.z), "f"(v.w) : "memory");
}

__global__ __launch_bounds__(256) void k_edge(const int* __restrict__ src,
                                              const int* __restrict__ dst)
{
    int t = blockIdx.x * blockDim.x + threadIdx.x;   // E*16 threads
    int e = t >> 4;
    int c = t & 15;
    if (e >= N_EDGES) return;
    int s = __ldg(&src[e]);
    int d = __ldg(&dst[e]);
    float coef = g_inv_out[s] * g_inv_in[d];
    float4 v = reinterpret_cast<const float4*>(g_x)[(size_t)s * 16 + c];
    v.x *= coef; v.y *= coef; v.z *= coef; v.w *= coef;
    red_add_v4(reinterpret_cast<float4*>(g_h2) + (size_t)d * 16 + c, v);
}

// ---------------- attention logits: w[n,c] = tanh(z_c @ att_w1 + b1) @ att_w2, sum over n ----------------
__global__ __launch_bounds__(128) void k_att(
    const float* __restrict__ att_w1,  // [64,32] k-major
    const float* __restrict__ att_b1,  // [32]
    const float* __restrict__ att_w2)  // [32]
{
    __shared__ float w1t[HC * HF];   // transposed: w1t[j*64+k] = att_w1[k*32+j], 8KB
    __shared__ float b1s[HC], w2s[HC];

    int tid = threadIdx.x;
    for (int i = tid; i < HC * HF; i += blockDim.x) {
        int j = i >> 6, k = i & 63;
        w1t[i] = att_w1[k * HC + j];
    }
    if (tid < HC) { b1s[tid] = att_b1[tid]; w2s[tid] = att_w2[tid]; }
    __syncthreads();

    int n = blockIdx.x * blockDim.x + tid;
    float w0 = 0.f, w1 = 0.f;
    if (n < N_NODES) {
        const float4* w1t4 = reinterpret_cast<const float4*>(w1t);
        // channel 0: h1
        {
            const float4* hr = reinterpret_cast<const float4*>(g_h1 + (size_t)n * HF);
            float4 h[16];
#pragma unroll
            for (int i = 0; i < 16; i++) h[i] = hr[i];
            for (int j = 0; j < HC; j++) {
                float s = b1s[j];
#pragma unroll
                for (int i = 0; i < 16; i++) {
                    float4 w = w1t4[j * 16 + i];
                    s += h[i].x * w.x + h[i].y * w.y + h[i].z * w.z + h[i].w * w.w;
                }
                w0 += tanhf(s) * w2s[j];
            }
        }
        // channel 1: h2
        {
            const float4* hr = reinterpret_cast<const float4*>(g_h2 + (size_t)n * HF);
            float4 h[16];
#pragma unroll
            for (int i = 0; i < 16; i++) h[i] = hr[i];
            for (int j = 0; j < HC; j++) {
                float s = b1s[j];
#pragma unroll
                for (int i = 0; i < 16; i++) {
                    float4 w = w1t4[j * 16 + i];
                    s += h[i].x * w.x + h[i].y * w.y + h[i].z * w.z + h[i].w * w.w;
                }
                w1 += tanhf(s) * w2s[j];
            }
        }
    }
    // warp reduce, then lane0 atomics
#pragma unroll
    for (int off = 16; off > 0; off >>= 1) {
        w0 += __shfl_down_sync(0xffffffff, w0, off);
        w1 += __shfl_down_sync(0xffffffff, w1, off);
    }
    if ((tid & 31) == 0) {
        atomicAdd(&g_wsum[0], w0);
        atomicAdd(&g_wsum[1], w1);
    }
}

// ---------------- final: beta softmax, blend, fc2 ----------------
__global__ __launch_bounds__(256) void k_out(
    const float* __restrict__ fc2_w,  // [16,64]
    const float* __restrict__ fc2_b,  // [16]
    float* __restrict__ out)
{
    __shared__ float4 ws[OF * 16];   // fc2_w rows as float4, 4KB
    __shared__ float bs[OF];

    int tid = threadIdx.x;
    for (int i = tid; i < OF * 16; i += blockDim.x)
        ws[i] = reinterpret_cast<const float4*>(fc2_w)[i];
    if (tid < OF) bs[tid] = fc2_b[tid];
    __syncthreads();

    int n = blockIdx.x * blockDim.x + tid;
    if (n >= N_NODES) return;

    float m0 = g_wsum[0] * (1.f / N_NODES);
    float m1 = g_wsum[1] * (1.f / N_NODES);
    float mx = fmaxf(m0, m1);
    float e0 = expf(m0 - mx), e1 = expf(m1 - mx);
    float inv = 1.f / (e0 + e1);
    float b0 = e0 * inv, b1 = e1 * inv;

    const float4* r1 = reinterpret_cast<const float4*>(g_h1 + (size_t)n * HF);
    const float4* r2 = reinterpret_cast<const float4*>(g_h2 + (size_t)n * HF);
    float4 f[16];
#pragma unroll
    for (int i = 0; i < 16; i++) {
        float4 a = r1[i], b = r2[i];
        f[i] = make_float4(b0 * a.x + b1 * b.x, b0 * a.y + b1 * b.y,
                           b0 * a.z + b1 * b.z, b0 * a.w + b1 * b.w);
    }
    float o[OF];
#pragma unroll
    for (int j = 0; j < OF; j++) {
        float acc = bs[j];
#pragma unroll
        for (int i = 0; i < 16; i++) {
            float4 w = ws[j * 16 + i];
            acc += f[i].x * w.x + f[i].y * w.y + f[i].z * w.z + f[i].w * w.w;
        }
        o[j] = acc;
    }
    float4* orow = reinterpret_cast<float4*>(out + (size_t)n * OF);
#pragma unroll
    for (int j = 0; j < 4; j++)
        orow[j] = make_float4(o[j * 4], o[j * 4 + 1], o[j * 4 + 2], o[j * 4 + 3]);
}

// ---------------- launch ----------------
extern "C" void kernel_launch(void* const* d_in, const int* in_sizes, int n_in,
                              void* d_out, int out_size)
{
    const float* feat   = (const float*)d_in[0];
    const int*   e_src  = (const int*)  d_in[1];
    const int*   e_dst  = (const int*)  d_in[2];
    const float* fc1_w  = (const float*)d_in[3];
    const float* fc1_b  = (const float*)d_in[4];
    const float* filt_w = (const float*)d_in[5];
    const float* filt_b = (const float*)d_in[6];
    const float* att_w1 = (const float*)d_in[7];
    const float* att_b1 = (const float*)d_in[8];
    const float* att_w2 = (const float*)d_in[9];
    const float* fc2_w  = (const float*)d_in[10];
    const float* fc2_b  = (const float*)d_in[11];
    float* out = (float*)d_out;

    // zero scratch (h2, degrees, wsum)
    k_zero<<<(N_NODES * 16 + 255) / 256, 256>>>();
    // degrees + normalization
    k_degree<<<(N_EDGES + 255) / 256, 256>>>(e_src, e_dst);
    k_invsqrt<<<(N_NODES + 255) / 256, 256>>>();
    // dual GEMM (independent of degree chain but same stream is fine)
    k_gemm<<<(N_NODES + 127) / 128, 128>>>(feat, fc1_w, fc1_b, filt_w, filt_b);
    // edge scatter
    k_edge<<<(N_EDGES * 16 + 255) / 256, 256>>>(e_src, e_dst);
    // attention logit sums
    k_att<<<(N_NODES + 127) / 128, 128>>>(att_w1, att_b1, att_w2);
    // blend + fc2
    k_out<<<(N_NODES + 255) / 256, 256>>>(fc2_w, fc2_b, out);
}

// round 2
// speedup vs baseline: 1.2334x; 1.2334x over previous
#include <cuda_runtime.h>
#include <math.h>

#define N_NODES 100000
#define N_EDGES 1600000

// ---------------- scratch (device globals; no runtime allocation) ----------------
__device__ float g_h1[(size_t)N_NODES * 64];   // tanh MLP branch
__device__ float g_xs[(size_t)N_NODES * 64];   // filter linear output pre-scaled by inv_out
__device__ float g_h2[(size_t)N_NODES * 64];   // raw aggregated branch (scale by inv_in on read)
__device__ float g_deg_out[N_NODES];
__device__ float g_deg_in [N_NODES];
__device__ float g_inv_out[N_NODES];
__device__ float g_inv_in [N_NODES];
__device__ float g_W[64 * 128];                // fused weight matrix [k][j]: j<64 fc1, j>=64 filt
__device__ float g_bias[128];
__device__ float g_wsum[2];

__device__ __forceinline__ float fast_tanh(float x) {
    float e = __expf(2.f * x);
    return 1.f - __fdividef(2.f, e + 1.f);
}

// ---------------- zero scratch ----------------
__global__ void k_init() {
    int i = blockIdx.x * blockDim.x + threadIdx.x;
    float4 z = make_float4(0.f, 0.f, 0.f, 0.f);
    if (i < N_NODES * 16) reinterpret_cast<float4*>(g_h2)[i] = z;
    if (i < N_NODES) { g_deg_out[i] = 0.f; g_deg_in[i] = 0.f; }
    if (i < 2) g_wsum[i] = 0.f;
}

// ---------------- degree histogram ----------------
__global__ void k_degree(const int* __restrict__ src, const int* __restrict__ dst) {
    int e = blockIdx.x * blockDim.x + threadIdx.x;
    if (e >= N_EDGES) return;
    atomicAdd(&g_deg_out[src[e]], 1.f);
    atomicAdd(&g_deg_in [dst[e]], 1.f);
}

// ---------------- inverse sqrt of degrees ----------------
__global__ void k_invsqrt() {
    int i = blockIdx.x * blockDim.x + threadIdx.x;
    if (i >= N_NODES) return;
    g_inv_out[i] = rsqrtf(fmaxf(g_deg_out[i], 1.f));
    g_inv_in [i] = rsqrtf(fmaxf(g_deg_in [i], 1.f));
}

// ---------------- build fused transposed weight matrix + bias ----------------
__global__ void k_prepW(const float* __restrict__ fc1_w, const float* __restrict__ fc1_b,
                        const float* __restrict__ filt_w, const float* __restrict__ filt_b) {
    int i = blockIdx.x * blockDim.x + threadIdx.x;
    if (i < 64 * 128) {
        int k = i >> 7, j = i & 127;
        g_W[i] = (j < 64) ? fc1_w[j * 64 + k] : filt_w[(j - 64) * 64 + k];
    }
    if (i < 128) g_bias[i] = (i < 64) ? fc1_b[i] : filt_b[i - 64];
}

// ---------------- tiled dual GEMM: [128 nodes x 128 cols] per block, 8x8 thread tile ----------------
__global__ __launch_bounds__(256) void k_gemm(const float* __restrict__ feat) {
    __shared__ float Bs[64][128];     // 32KB: W[k][j]
    __shared__ float As[16][128];     // 8KB:  feat chunk transposed [k][m]
    __shared__ float bias_s[128];

    int tid = threadIdx.x;
    int m0 = blockIdx.x * 128;

    for (int i = tid; i < 64 * 128; i += 256) ((float*)Bs)[i] = g_W[i];
    if (tid < 128) bias_s[tid] = g_bias[tid];

    int tx = tid & 15, ty = tid >> 4;     // tx: 16 col-groups of 8, ty: 16 row-groups of 8
    int r  = tid & 127, hf = tid >> 7;    // staging: row r, half hf

    float acc[8][8];
#pragma unroll
    for (int i = 0; i < 8; i++)
#pragma unroll
        for (int j = 0; j < 8; j++) acc[i][j] = 0.f;

    int m_load = m0 + r;
    bool valid = m_load < N_NODES;
    const float4* frow = reinterpret_cast<const float4*>(feat + (size_t)m_load * 64);
    float4 z4 = make_float4(0.f, 0.f, 0.f, 0.f);

    for (int kc = 0; kc < 64; kc += 16) {
        __syncthreads();
        float4 v0 = valid ? frow[(kc >> 2) + hf * 2]     : z4;
        float4 v1 = valid ? frow[(kc >> 2) + hf * 2 + 1] : z4;
        int kb = hf * 8;
        As[kb + 0][r] = v0.x; As[kb + 1][r] = v0.y; As[kb + 2][r] = v0.z; As[kb + 3][r] = v0.w;
        As[kb + 4][r] = v1.x; As[kb + 5][r] = v1.y; As[kb + 6][r] = v1.z; As[kb + 7][r] = v1.w;
        __syncthreads();

#pragma unroll
        for (int k = 0; k < 16; k++) {
            float4 a0 = *reinterpret_cast<const float4*>(&As[k][ty * 8]);
            float4 a1 = *reinterpret_cast<const float4*>(&As[k][ty * 8 + 4]);
            float4 b0 = *reinterpret_cast<const float4*>(&Bs[kc + k][tx * 8]);
            float4 b1 = *reinterpret_cast<const float4*>(&Bs[kc + k][tx * 8 + 4]);
            float a[8] = {a0.x, a0.y, a0.z, a0.w, a1.x, a1.y, a1.z, a1.w};
            float b[8] = {b0.x, b0.y, b0.z, b0.w, b1.x, b1.y, b1.z, b1.w};
#pragma unroll
            for (int i = 0; i < 8; i++)
#pragma unroll
                for (int j = 0; j < 8; j++) acc[i][j] += a[i] * b[j];
        }
    }

    int jb = tx * 8;
#pragma unroll
    for (int i = 0; i < 8; i++) {
        int m = m0 + ty * 8 + i;
        if (m >= N_NODES) continue;
        if (jb < 64) {
            float o[8];
#pragma unroll
            for (int j = 0; j < 8; j++) o[j] = fast_tanh(acc[i][j] + bias_s[jb + j]);
            float4* p = reinterpret_cast<float4*>(g_h1 + (size_t)m * 64 + jb);
            p[0] = make_float4(o[0], o[1], o[2], o[3]);
            p[1] = make_float4(o[4], o[5], o[6], o[7]);
        } else {
            float s = g_inv_out[m];
            float o[8];
#pragma unroll
            for (int j = 0; j < 8; j++) o[j] = (acc[i][j] + bias_s[jb + j]) * s;
            float4* p = reinterpret_cast<float4*>(g_xs + (size_t)m * 64 + (jb - 64));
            p[0] = make_float4(o[0], o[1], o[2], o[3]);
            p[1] = make_float4(o[4], o[5], o[6], o[7]);
        }
    }
}

// ---------------- edge scatter: h2[dst] += xs[src] ----------------
__device__ __forceinline__ void red_add_v4(float4* addr, float4 v) {
    asm volatile("red.global.add.v4.f32 [%0], {%1,%2,%3,%4};"
                 :: "l"(addr), "f"(v.x), "f"(v.y), "f"(v.z), "f"(v.w) : "memory");
}

__global__ __launch_bounds__(256) void k_edge(const int* __restrict__ src,
                                              const int* __restrict__ dst) {
    int t = blockIdx.x * blockDim.x + threadIdx.x;
    int e = t >> 4;
    if (e >= N_EDGES) return;
    int c = t & 15;
    int s = __ldg(&src[e]);
    int d = __ldg(&dst[e]);
    float4 v = reinterpret_cast<const float4*>(g_xs)[(size_t)s * 16 + c];
    red_add_v4(reinterpret_cast<float4*>(g_h2) + (size_t)d * 16 + c, v);
}

// ---------------- attention logit global sums (tiled), grid.y = channel ----------------
__global__ __launch_bounds__(128) void k_att(const float* __restrict__ att_w1,
                                             const float* __restrict__ att_b1,
                                             const float* __restrict__ att_w2) {
    __shared__ float Ws[64][32];    // 8KB: att_w1 already [k][j]
    __shared__ float As[8][128];    // 4KB: h chunk transposed
    __shared__ float b1s[32], w2s[32];
    __shared__ float redbuf[4];

    int tid = threadIdx.x;
    int ch  = blockIdx.y;
    int m0  = blockIdx.x * 128;

    for (int i = tid; i < 64 * 32; i += 128) ((float*)Ws)[i] = att_w1[i];
    if (tid < 32) { b1s[tid] = att_b1[tid]; w2s[tid] = att_w2[tid]; }

    int tx = tid & 7, ty = tid >> 3;  // 8 col-groups of 4, 16 row-groups of 8
    const float* hsrc = ch ? g_h2 : g_h1;

    int m_load = m0 + tid;
    bool valid = m_load < N_NODES;
    float scale = 1.f;
    if (ch && valid) scale = g_inv_in[m_load];
    const float4* hrow = reinterpret_cast<const float4*>(hsrc + (size_t)m_load * 64);
    float4 z4 = make_float4(0.f, 0.f, 0.f, 0.f);

    float acc[8][4];
#pragma unroll
    for (int i = 0; i < 8; i++)
#pragma unroll
        for (int j = 0; j < 4; j++) acc[i][j] = 0.f;

    for (int kc = 0; kc < 64; kc += 8) {
        __syncthreads();
        float4 v0 = valid ? hrow[kc >> 2]       : z4;
        float4 v1 = valid ? hrow[(kc >> 2) + 1] : z4;
        As[0][tid] = v0.x * scale; As[1][tid] = v0.y * scale;
        As[2][tid] = v0.z * scale; As[3][tid] = v0.w * scale;
        As[4][tid] = v1.x * scale; As[5][tid] = v1.y * scale;
        As[6][tid] = v1.z * scale; As[7][tid] = v1.w * scale;
        __syncthreads();

#pragma unroll
        for (int k = 0; k < 8; k++) {
            float4 a0 = *reinterpret_cast<const float4*>(&As[k][ty * 8]);
            float4 a1 = *reinterpret_cast<const float4*>(&As[k][ty * 8 + 4]);
            float4 b  = *reinterpret_cast<const float4*>(&Ws[kc + k][tx * 4]);
            float a[8] = {a0.x, a0.y, a0.z, a0.w, a1.x, a1.y, a1.z, a1.w};
            float bb[4] = {b.x, b.y, b.z, b.w};
#pragma unroll
            for (int i = 0; i < 8; i++)
#pragma unroll
                for (int j = 0; j < 4; j++) acc[i][j] += a[i] * bb[j];
        }
    }

    float part = 0.f;
#pragma unroll
    for (int i = 0; i < 8; i++) {
        int m = m0 + ty * 8 + i;
        if (m >= N_NODES) continue;
#pragma unroll
        for (int j = 0; j < 4; j++)
            part += fast_tanh(acc[i][j] + b1s[tx * 4 + j]) * w2s[tx * 4 + j];
    }
#pragma unroll
    for (int off = 16; off > 0; off >>= 1)
        part += __shfl_down_sync(0xffffffff, part, off);
    if ((tid & 31) == 0) redbuf[tid >> 5] = part;
    __syncthreads();
    if (tid == 0)
        atomicAdd(&g_wsum[ch], redbuf[0] + redbuf[1] + redbuf[2] + redbuf[3]);
}

// ---------------- final: beta softmax, blend (inv_in folded), fc2 ----------------
__global__ __launch_bounds__(256) void k_out(const float* __restrict__ fc2_w,
                                             const float* __restrict__ fc2_b,
                                             float* __restrict__ out) {
    __shared__ float4 ws[16 * 16];   // fc2_w rows as float4, 4KB
    __shared__ float bs[16];

    int tid = threadIdx.x;
    for (int i = tid; i < 16 * 16; i += 256)
        ws[i] = reinterpret_cast<const float4*>(fc2_w)[i];
    if (tid < 16) bs[tid] = fc2_b[tid];
    __syncthreads();

    int n = blockIdx.x * blockDim.x + tid;
    if (n >= N_NODES) return;

    float m0 = g_wsum[0] * (1.f / N_NODES);
    float m1 = g_wsum[1] * (1.f / N_NODES);
    float mx = fmaxf(m0, m1);
    float e0 = expf(m0 - mx), e1 = expf(m1 - mx);
    float inv = 1.f / (e0 + e1);
    float b0 = e0 * inv;
    float b1 = e1 * inv * g_inv_in[n];   // fold inv_in into channel-1 weight

    const float4* r1 = reinterpret_cast<const float4*>(g_h1 + (size_t)n * 64);
    const float4* r2 = reinterpret_cast<const float4*>(g_h2 + (size_t)n * 64);
    float4 f[16];
#pragma unroll
    for (int i = 0; i < 16; i++) {
        float4 a = r1[i], b = r2[i];
        f[i] = make_float4(b0 * a.x + b1 * b.x, b0 * a.y + b1 * b.y,
                           b0 * a.z + b1 * b.z, b0 * a.w + b1 * b.w);
    }
    float o[16];
#pragma unroll
    for (int j = 0; j < 16; j++) {
        float acc = bs[j];
#pragma unroll
        for (int i = 0; i < 16; i++) {
            float4 w = ws[j * 16 + i];
            acc += f[i].x * w.x + f[i].y * w.y + f[i].z * w.z + f[i].w * w.w;
        }
        o[j] = acc;
    }
    float4* orow = reinterpret_cast<float4*>(out + (size_t)n * 16);
#pragma unroll
    for (int j = 0; j < 4; j++)
        orow[j] = make_float4(o[j * 4], o[j * 4 + 1], o[j * 4 + 2], o[j * 4 + 3]);
}

// ---------------- launch ----------------
extern "C" void kernel_launch(void* const* d_in, const int* in_sizes, int n_in,
                              void* d_out, int out_size)
{
    const float* feat   = (const float*)d_in[0];
    const int*   e_src  = (const int*)  d_in[1];
    const int*   e_dst  = (const int*)  d_in[2];
    const float* fc1_w  = (const float*)d_in[3];
    const float* fc1_b  = (const float*)d_in[4];
    const float* filt_w = (const float*)d_in[5];
    const float* filt_b = (const float*)d_in[6];
    const float* att_w1 = (const float*)d_in[7];
    const float* att_b1 = (const float*)d_in[8];
    const float* att_w2 = (const float*)d_in[9];
    const float* fc2_w  = (const float*)d_in[10];
    const float* fc2_b  = (const float*)d_in[11];
    float* out = (float*)d_out;

    k_init<<<(N_NODES * 16 + 255) / 256, 256>>>();
    k_degree<<<(N_EDGES + 255) / 256, 256>>>(e_src, e_dst);
    k_invsqrt<<<(N_NODES + 255) / 256, 256>>>();
    k_prepW<<<(64 * 128 + 255) / 256, 256>>>(fc1_w, fc1_b, filt_w, filt_b);
    k_gemm<<<(N_NODES + 127) / 128, 256>>>(feat);
    k_edge<<<(N_EDGES * 16 + 255) / 256, 256>>>(e_src, e_dst);
    dim3 att_grid((N_NODES + 127) / 128, 2);
    k_att<<<att_grid, 128>>>(att_w1, att_b1, att_w2);
    k_out<<<(N_NODES + 255) / 256, 256>>>(fc2_w, fc2_b, out);
}